// round 14
// baseline (speedup 1.0000x reference)
#include <cuda_runtime.h>
#include <cstdint>

// ---------------------------------------------------------------------------
// TorchNeighborList: N=4096 atoms, no PBC. Output layout (as float32):
//   [0,      M)   idx_i   (valid prefix [0,T), sentinel N in [T,M))
//   [M,     2M)   idx_j   (same split)
//   [2M,    5M)   Rij     (valid prefix [0,3T), zeros after)
//   [5M,    8M)   cell_offset (all zeros)
//   [8M,    9M)   mask    (1.0 in [0,T), 0.0 after)
//   [9M]          num_pairs = T
// where M = 2P = N*(N-1), T = number of in-cutoff directed pairs.
//
// Ordering reproduced analytically: centers ascending; within center k,
// neighbors in order j = (k+t) mod N for t = 1..N-1 (exactly the reference's
// stable argsort over concat(triu_i, triu_j)).
//
// Schedule (R12 structure; SoA counts):
//   L0 soa    : transpose positions -> SoA (g_px/g_py/g_pz)
//   L1 fused  : sentinel fill [0,2M) (134 MB) || counts (SoA, coalesced)
//   M1 memset : zero [2M,9M) (469 MB) via driver memset (~6.9 TB/s measured)
//   L2 scan   : single block, prefetched register/shfl scan -> offsets, T
//   L3 emit   : thread-per-valid-pair -> compacted writes at [0,T)
// ---------------------------------------------------------------------------

#define CHUNK 512
#define MPW   (CHUNK / 32)          // ballots per segment (16)
#define MAX_N 8192
#define MAX_SEG 65536
#define NTILES 32                   // S / 1024 for N=4096

__device__ int g_counts[MAX_SEG];
__device__ int g_offsets[MAX_SEG];
__device__ unsigned g_masks[MAX_SEG * MPW];
__device__ int g_total;
__device__ float g_px[MAX_N], g_py[MAX_N], g_pz[MAX_N];

// exact (non-contracted) squared distance, matching jnp.linalg.norm assoc order
__device__ __forceinline__ float dist2(float dx, float dy, float dz) {
    return __fadd_rn(__fadd_rn(__fmul_rn(dx, dx), __fmul_rn(dy, dy)),
                     __fmul_rn(dz, dz));
}

// -------- Kernel 0: AoS -> SoA transpose ----------------------------------
__global__ __launch_bounds__(256) void soa_kernel(const float* __restrict__ pos,
                                                  int N) {
    int i = (int)(blockIdx.x * blockDim.x + threadIdx.x);
    if (i < N) {
        g_px[i] = pos[3 * i + 0];
        g_py[i] = pos[3 * i + 1];
        g_pz[i] = pos[3 * i + 2];
    }
}

// -------- Kernel 1: sentinel fill [0,2M) || counts (SoA) ------------------
__global__ __launch_bounds__(256) void fill_count_kernel(
    float* __restrict__ out, size_t M, int N, int C, int FB) {
    if ((int)blockIdx.x < FB) {
        // ---- sentinel fill over idx_i/idx_j region [0, 2M) ----
        float4* __restrict__ out4 = (float4*)out;
        const float sn = (float)N;
        const float4 sv = make_float4(sn, sn, sn, sn);
        size_t hi4 = (2 * M) / 4;
        size_t stride = (size_t)FB * 512;           // 2 vec4 per thread/iter
        size_t base = (size_t)blockIdx.x * 512 + threadIdx.x;
        for (size_t i = base; i < hi4; i += stride) {
            out4[i] = sv;
            size_t i2 = i + 256;
            if (i2 < hi4) out4[i2] = sv;
        }
    } else {
        // ---- counts + ballot cache: warp per (center,chunk), SoA loads ----
        int warp = (int)((((size_t)blockIdx.x - FB) * blockDim.x + threadIdx.x) >> 5);
        int lane = threadIdx.x & 31;
        if (warp >= N * C) return;
        int k = warp / C;
        int c = warp - k * C;

        float xk = __ldg(&g_px[k]), yk = __ldg(&g_py[k]), zk = __ldg(&g_pz[k]);

        int cnt = 0;
        int tbase = c * CHUNK;
#pragma unroll 4
        for (int u = 0; u < MPW; u++) {
            int t = tbase + u * 32 + lane;
            bool valid = false;
            if (t > 0 && t < N) {
                int j = k + t;
                if (j >= N) j -= N;
                float dx = __fsub_rn(__ldg(&g_px[j]), xk);
                float dy = __fsub_rn(__ldg(&g_py[j]), yk);
                float dz = __fsub_rn(__ldg(&g_pz[j]), zk);
                valid = dist2(dx, dy, dz) < 25.0f;
            }
            unsigned m = __ballot_sync(0xffffffffu, valid);
            if (lane == 0) g_masks[warp * MPW + u] = m;
            cnt += __popc(m);
        }
        if (lane == 0) g_counts[warp] = cnt;
    }
}

// -------- Kernel 2: prefetched register scan (1 block, 1024 thr) ----------
__global__ __launch_bounds__(1024) void scan_kernel(float* __restrict__ out,
                                                    size_t M, int S) {
    __shared__ int wsum[32];
    __shared__ int wbase[32];
    __shared__ int tile_tot[NTILES];
    int t = threadIdx.x;
    int warp = t >> 5, lane = t & 31;

    // prefetch ALL counts (coalesced, independent -> single latency exposure)
    int c[NTILES];
#pragma unroll
    for (int u = 0; u < NTILES; u++) {
        int i = u * 1024 + t;
        c[u] = (i < S) ? g_counts[i] : 0;
    }

    int excl[NTILES];
#pragma unroll
    for (int u = 0; u < NTILES; u++) {
        int incl = c[u];
#pragma unroll
        for (int o = 1; o < 32; o <<= 1) {
            int v = __shfl_up_sync(0xffffffffu, incl, o);
            if (lane >= o) incl += v;
        }
        if (lane == 31) wsum[warp] = incl;
        __syncthreads();
        if (warp == 0) {
            int v = wsum[lane];
            int winc = v;
#pragma unroll
            for (int o = 1; o < 32; o <<= 1) {
                int x = __shfl_up_sync(0xffffffffu, winc, o);
                if (lane >= o) winc += x;
            }
            wbase[lane] = winc - v;
            if (lane == 31) tile_tot[u] = winc;
        }
        __syncthreads();
        excl[u] = wbase[warp] + (incl - c[u]);
    }

    int running = 0;
#pragma unroll
    for (int u = 0; u < NTILES; u++) {
        int i = u * 1024 + t;
        if (i < S) g_offsets[i] = running + excl[u];
        running += tile_tot[u];
    }
    if (t == 0) {
        g_total = running;
        out[9 * M] = (float)running;  // num_pairs
    }
}

// -------- Kernel 3: thread-per-valid-pair emit ----------------------------
__global__ __launch_bounds__(256) void emit_kernel(float* __restrict__ out,
                                                   size_t M, int N, int C, int S) {
    int T = g_total;
    float* __restrict__ idx_i = out;
    float* __restrict__ idx_j = out + M;
    float* __restrict__ rij   = out + 2 * M;
    float* __restrict__ maskp = out + 8 * M;

    int stride = (int)(gridDim.x * blockDim.x);
    for (int p = (int)(blockIdx.x * blockDim.x + threadIdx.x); p < T;
         p += stride) {
        // binary search: largest w with g_offsets[w] <= p
        int lo = 0, hi = S;
        while (hi - lo > 1) {
            int mid = (lo + hi) >> 1;
            if (g_offsets[mid] <= p) lo = mid; else hi = mid;
        }
        int w = lo;
        int r = p - g_offsets[w];
        int k = w / C;
        int c = w - k * C;

        // locate the ballot containing rank r
        int u = 0;
        unsigned m;
        for (;;) {
            m = g_masks[w * MPW + u];
            int cnt = __popc(m);
            if (r < cnt) break;
            r -= cnt;
            u++;
        }
        unsigned mm = m;
        for (int q = 0; q < r; q++) mm &= mm - 1;
        int lane = __ffs(mm) - 1;

        int t = c * CHUNK + u * 32 + lane;
        int j = k + t;
        if (j >= N) j -= N;

        float dx = __fsub_rn(__ldg(&g_px[j]), __ldg(&g_px[k]));  // pos[j]-pos[k]
        float dy = __fsub_rn(__ldg(&g_py[j]), __ldg(&g_py[k]));
        float dz = __fsub_rn(__ldg(&g_pz[j]), __ldg(&g_pz[k]));

        idx_i[p] = (float)k;
        idx_j[p] = (float)j;
        rij[3 * (size_t)p + 0] = dx;
        rij[3 * (size_t)p + 1] = dy;
        rij[3 * (size_t)p + 2] = dz;
        maskp[p] = 1.0f;
    }
}

// ---------------------------------------------------------------------------
extern "C" void kernel_launch(void* const* d_in, const int* in_sizes, int n_in,
                              void* d_out, int out_size) {
    const float* pos = (const float*)d_in[0];
    int N = in_sizes[0] / 3;                   // 4096
    size_t M = ((size_t)out_size - 1) / 9;     // 2P = N*(N-1)
    float* out = (float*)d_out;

    int C = (N + CHUNK - 1) / CHUNK;           // 8 chunks per center
    int S = N * C;                             // 32768 segments

    int count_blocks = (S * 32 + 255) / 256;   // 4096: warp per segment
    int fill_blocks  = 2048;                   // sentinel fill [0,2M)

    soa_kernel<<<(N + 255) / 256, 256>>>(pos, N);
    fill_count_kernel<<<fill_blocks + count_blocks, 256>>>(out, M, N, C,
                                                           fill_blocks);
    cudaMemsetAsync(out + 2 * M, 0, 7 * M * sizeof(float));
    scan_kernel<<<1, 1024>>>(out, M, S);
    emit_kernel<<<2048, 256>>>(out, M, N, C, S);
}

// round 15
// speedup vs baseline: 1.1491x; 1.1491x over previous
#include <cuda_runtime.h>
#include <cstdint>

// ---------------------------------------------------------------------------
// TorchNeighborList: N=4096 atoms, no PBC. Output layout (as float32):
//   [0,      M)   idx_i   (valid prefix [0,T), sentinel N in [T,M))
//   [M,     2M)   idx_j   (same split)
//   [2M,    5M)   Rij     (valid prefix [0,3T), zeros after)
//   [5M,    8M)   cell_offset (all zeros)
//   [8M,    9M)   mask    (1.0 in [0,T), 0.0 after)
//   [9M]          num_pairs = T
// where M = 2P = N*(N-1), T = number of in-cutoff directed pairs.
//
// Ordering reproduced analytically: centers ascending; within center k,
// neighbors in order j = (k+t) mod N for t = 1..N-1 (exactly the reference's
// stable argsort over concat(triu_i, triu_j)).
//
// Forked-capture schedule:
//   stream B : memset Rij+mask (268 MB) -> eA -> memset cell_offset (201 MB)
//   stream 0 : L1 fill sentinel [0,2M) || counts -> scan -> (wait eA) emit
//   join eJoin at end. Memsets (6.9 TB/s path) overlap counts/scan/emit.
//   emit is ordered after the Rij/mask memset, so prefix overwrite is safe.
// ---------------------------------------------------------------------------

#define CHUNK 512
#define MPW   (CHUNK / 32)          // ballots per segment (16)
#define MAX_SEG 65536
#define NTILES 32                   // S / 1024 for N=4096

__device__ int g_counts[MAX_SEG];
__device__ int g_offsets[MAX_SEG];
__device__ unsigned g_masks[MAX_SEG * MPW];
__device__ int g_total;

// exact (non-contracted) squared distance, matching jnp.linalg.norm assoc order
__device__ __forceinline__ float dist2(float dx, float dy, float dz) {
    return __fadd_rn(__fadd_rn(__fmul_rn(dx, dx), __fmul_rn(dy, dy)),
                     __fmul_rn(dz, dz));
}

// -------- Kernel 1: sentinel fill [0,2M) || counts ------------------------
__global__ __launch_bounds__(256) void fill_count_kernel(
    const float* __restrict__ pos, float* __restrict__ out,
    size_t M, int N, int C, int FB) {
    if ((int)blockIdx.x < FB) {
        float4* __restrict__ out4 = (float4*)out;
        const float sn = (float)N;
        const float4 sv = make_float4(sn, sn, sn, sn);
        size_t hi4 = (2 * M) / 4;
        size_t stride = (size_t)FB * 512;           // 2 vec4 per thread/iter
        size_t base = (size_t)blockIdx.x * 512 + threadIdx.x;
        for (size_t i = base; i < hi4; i += stride) {
            out4[i] = sv;
            size_t i2 = i + 256;
            if (i2 < hi4) out4[i2] = sv;
        }
    } else {
        // ---- counts + ballot cache: warp per (center,chunk) ----
        int warp = (int)((((size_t)blockIdx.x - FB) * blockDim.x + threadIdx.x) >> 5);
        int lane = threadIdx.x & 31;
        if (warp >= N * C) return;
        int k = warp / C;
        int c = warp - k * C;

        const float* pk = pos + 3 * (size_t)k;
        float xk = __ldg(pk), yk = __ldg(pk + 1), zk = __ldg(pk + 2);

        int cnt = 0;
        int tbase = c * CHUNK;
#pragma unroll 4
        for (int u = 0; u < MPW; u++) {
            int t = tbase + u * 32 + lane;
            bool valid = false;
            if (t > 0 && t < N) {
                int j = k + t;
                if (j >= N) j -= N;
                const float* pj = pos + 3 * (size_t)j;
                float dx = __fsub_rn(__ldg(pj),     xk);
                float dy = __fsub_rn(__ldg(pj + 1), yk);
                float dz = __fsub_rn(__ldg(pj + 2), zk);
                valid = dist2(dx, dy, dz) < 25.0f;
            }
            unsigned m = __ballot_sync(0xffffffffu, valid);
            if (lane == 0) g_masks[warp * MPW + u] = m;
            cnt += __popc(m);
        }
        if (lane == 0) g_counts[warp] = cnt;
    }
}

// -------- Kernel 2: prefetched register scan (1 block, 1024 thr) ----------
__global__ __launch_bounds__(1024) void scan_kernel(float* __restrict__ out,
                                                    size_t M, int S) {
    __shared__ int wsum[32];
    __shared__ int wbase[32];
    __shared__ int tile_tot[NTILES];
    int t = threadIdx.x;
    int warp = t >> 5, lane = t & 31;

    int c[NTILES];
#pragma unroll
    for (int u = 0; u < NTILES; u++) {
        int i = u * 1024 + t;
        c[u] = (i < S) ? g_counts[i] : 0;
    }

    int excl[NTILES];
#pragma unroll
    for (int u = 0; u < NTILES; u++) {
        int incl = c[u];
#pragma unroll
        for (int o = 1; o < 32; o <<= 1) {
            int v = __shfl_up_sync(0xffffffffu, incl, o);
            if (lane >= o) incl += v;
        }
        if (lane == 31) wsum[warp] = incl;
        __syncthreads();
        if (warp == 0) {
            int v = wsum[lane];
            int winc = v;
#pragma unroll
            for (int o = 1; o < 32; o <<= 1) {
                int x = __shfl_up_sync(0xffffffffu, winc, o);
                if (lane >= o) winc += x;
            }
            wbase[lane] = winc - v;
            if (lane == 31) tile_tot[u] = winc;
        }
        __syncthreads();
        excl[u] = wbase[warp] + (incl - c[u]);
    }

    int running = 0;
#pragma unroll
    for (int u = 0; u < NTILES; u++) {
        int i = u * 1024 + t;
        if (i < S) g_offsets[i] = running + excl[u];
        running += tile_tot[u];
    }
    if (t == 0) {
        g_total = running;
        out[9 * M] = (float)running;  // num_pairs
    }
}

// -------- Kernel 3: thread-per-valid-pair emit ----------------------------
__global__ __launch_bounds__(256) void emit_kernel(const float* __restrict__ pos,
                                                   float* __restrict__ out,
                                                   size_t M, int N, int C, int S) {
    int T = g_total;
    float* __restrict__ idx_i = out;
    float* __restrict__ idx_j = out + M;
    float* __restrict__ rij   = out + 2 * M;
    float* __restrict__ maskp = out + 8 * M;

    int stride = (int)(gridDim.x * blockDim.x);
    for (int p = (int)(blockIdx.x * blockDim.x + threadIdx.x); p < T;
         p += stride) {
        // binary search: largest w with g_offsets[w] <= p
        int lo = 0, hi = S;
        while (hi - lo > 1) {
            int mid = (lo + hi) >> 1;
            if (g_offsets[mid] <= p) lo = mid; else hi = mid;
        }
        int w = lo;
        int r = p - g_offsets[w];
        int k = w / C;
        int c = w - k * C;

        int u = 0;
        unsigned m;
        for (;;) {
            m = g_masks[w * MPW + u];
            int cnt = __popc(m);
            if (r < cnt) break;
            r -= cnt;
            u++;
        }
        unsigned mm = m;
        for (int q = 0; q < r; q++) mm &= mm - 1;
        int lane = __ffs(mm) - 1;

        int t = c * CHUNK + u * 32 + lane;
        int j = k + t;
        if (j >= N) j -= N;

        const float* pk = pos + 3 * (size_t)k;
        const float* pj = pos + 3 * (size_t)j;
        float dx = __fsub_rn(__ldg(pj),     __ldg(pk));      // pos[j]-pos[k]
        float dy = __fsub_rn(__ldg(pj + 1), __ldg(pk + 1));
        float dz = __fsub_rn(__ldg(pj + 2), __ldg(pk + 2));

        idx_i[p] = (float)k;
        idx_j[p] = (float)j;
        rij[3 * (size_t)p + 0] = dx;
        rij[3 * (size_t)p + 1] = dy;
        rij[3 * (size_t)p + 2] = dz;
        maskp[p] = 1.0f;
    }
}

// ---------------------------------------------------------------------------
extern "C" void kernel_launch(void* const* d_in, const int* in_sizes, int n_in,
                              void* d_out, int out_size) {
    const float* pos = (const float*)d_in[0];
    int N = in_sizes[0] / 3;                   // 4096
    size_t M = ((size_t)out_size - 1) / 9;     // 2P = N*(N-1)
    float* out = (float*)d_out;

    int C = (N + CHUNK - 1) / CHUNK;           // 8 chunks per center
    int S = N * C;                             // 32768 segments

    int count_blocks = (S * 32 + 255) / 256;   // 4096: warp per segment
    int fill_blocks  = 2048;                   // sentinel fill [0,2M)

    // side stream + fork/join events (host resources; no device memory)
    cudaStream_t sB;
    cudaStreamCreateWithFlags(&sB, cudaStreamNonBlocking);
    cudaEvent_t eFork, eA, eJoin;
    cudaEventCreateWithFlags(&eFork, cudaEventDisableTiming);
    cudaEventCreateWithFlags(&eA,    cudaEventDisableTiming);
    cudaEventCreateWithFlags(&eJoin, cudaEventDisableTiming);

    // fork capture into sB
    cudaEventRecord(eFork, 0);
    cudaStreamWaitEvent(sB, eFork, 0);

    // stream B: Rij + mask zeros (needed before emit), then cell_offset zeros
    cudaMemsetAsync(out + 2 * M, 0, 3 * M * sizeof(float), sB);  // Rij
    cudaMemsetAsync(out + 8 * M, 0,     M * sizeof(float), sB);  // mask
    cudaEventRecord(eA, sB);
    cudaMemsetAsync(out + 5 * M, 0, 3 * M * sizeof(float), sB);  // cell_offset
    cudaEventRecord(eJoin, sB);

    // stream 0: sentinel fill || counts, then scan
    fill_count_kernel<<<fill_blocks + count_blocks, 256>>>(pos, out, M, N, C,
                                                           fill_blocks);
    scan_kernel<<<1, 1024>>>(out, M, S);

    // emit must follow the Rij/mask memsets (valid-prefix overwrite)
    cudaStreamWaitEvent(0, eA, 0);
    emit_kernel<<<2048, 256>>>(pos, out, M, N, C, S);

    // join remaining memset before the launch returns to the harness stream
    cudaStreamWaitEvent(0, eJoin, 0);
}